// round 1
// baseline (speedup 1.0000x reference)
#include <cuda_runtime.h>
#include <math.h>
#include <float.h>

#define Bn   8
#define Ln   32768
#define Dn   128
#define BSn  512
#define BCn  64
#define NBn  512        // B*BC
#define Kc   6
#define CKn  768        // D*K (im2col depth)
#define TILE_T 256
#define NTILES 128      // Ln / TILE_T
#define SCALE_F 0.08838834764831845f  // 1/sqrt(128)

// ---------------- scratch (device globals; no allocations allowed) ----------
__device__ float g_prefix[Bn*Ln*Dn];     // 128 MB
__device__ float g_conv  [NBn*BSn*Dn];   // 128 MB
__device__ float g_logits[Bn*Ln];
__device__ float g_ex    [Bn*Ln];
__device__ float g_psum  [Bn*Ln];
__device__ float g_part  [Bn*NTILES*Dn];
__device__ float g_repr  [NBn*Dn];
__device__ float g_Bt    [CKn*Dn];       // reorganized conv weights [ci][o]

// ---------------- helpers ----------------------------------------------------
__device__ __forceinline__ void atomicMaxF(float* a, float v) {
    if (v >= 0.f) atomicMax((int*)a, __float_as_int(v));
    else          atomicMin((unsigned int*)a, __float_as_uint(v));
}

// block reduce for 256-thread blocks (8 warps). red: smem float[8].
__device__ __forceinline__ float bredMax(float v, float* red) {
    int lane = threadIdx.x & 31, wid = threadIdx.x >> 5;
    #pragma unroll
    for (int o = 16; o; o >>= 1) v = fmaxf(v, __shfl_xor_sync(0xffffffffu, v, o));
    if (lane == 0) red[wid] = v;
    __syncthreads();
    float r = red[0];
    #pragma unroll
    for (int w = 1; w < 8; w++) r = fmaxf(r, red[w]);
    __syncthreads();
    return r;
}
__device__ __forceinline__ float bredSum(float v, float* red) {
    int lane = threadIdx.x & 31, wid = threadIdx.x >> 5;
    #pragma unroll
    for (int o = 16; o; o >>= 1) v += __shfl_xor_sync(0xffffffffu, v, o);
    if (lane == 0) red[wid] = v;
    __syncthreads();
    float r = red[0];
    #pragma unroll
    for (int w = 1; w < 8; w++) r += red[w];
    __syncthreads();
    return r;
}

// ---------------- K0: weight reorg + repr init -------------------------------
__global__ void k_prep(const float* __restrict__ cw) {
    int idx = blockIdx.x * blockDim.x + threadIdx.x;      // over CKn*Dn
    if (idx >= CKn * Dn) return;
    int ci = idx >> 7, o = idx & 127;
    int k = ci >> 7, i = ci & 127;                         // ci = k*128 + i
    g_Bt[idx] = cw[o * CKn + i * Kc + k];                  // conv_w[o][i][k]
}
__global__ void k_init_repr() {
    int i = blockIdx.x * blockDim.x + threadIdx.x;
    if (i < NBn * Dn) g_repr[i] = -FLT_MAX;
}

// ---------------- K1: logits = silu(x . w + b) -------------------------------
__global__ void k_logits(const float* __restrict__ x, const float* __restrict__ w,
                         const float* __restrict__ b) {
    int tok  = (blockIdx.x * blockDim.x + threadIdx.x) >> 5;
    int lane = threadIdx.x & 31;
    if (tok >= Bn * Ln) return;
    const float4* xr = (const float4*)(x + (size_t)tok * Dn);
    const float4* wr = (const float4*)w;
    float4 a = xr[lane], ww = wr[lane];
    float d = a.x*ww.x + a.y*ww.y + a.z*ww.z + a.w*ww.w;
    #pragma unroll
    for (int o = 16; o; o >>= 1) d += __shfl_xor_sync(0xffffffffu, d, o);
    if (lane == 0) {
        float l = d + b[0];
        g_logits[tok] = l / (1.f + expf(-l));              // silu
    }
}

// ---------------- K2: per-batch scalar scans (cummax -> ex -> cumsum) --------
__global__ __launch_bounds__(1024) void k_scan_scalar() {
    __shared__ float wbuf[32];
    int b = blockIdx.x, tid = threadIdx.x, lane = tid & 31, wid = tid >> 5;
    float l[32];
    const float* lp = g_logits + b * Ln + tid * 32;
    #pragma unroll
    for (int i = 0; i < 32; i++) l[i] = lp[i];
    float tmax = -FLT_MAX;
    #pragma unroll
    for (int i = 0; i < 32; i++) tmax = fmaxf(tmax, l[i]);

    // block exclusive max-scan of per-thread maxima
    float inc = tmax;
    #pragma unroll
    for (int o = 1; o < 32; o <<= 1) {
        float t = __shfl_up_sync(0xffffffffu, inc, o);
        if (lane >= o) inc = fmaxf(inc, t);
    }
    if (lane == 31) wbuf[wid] = inc;
    __syncthreads();
    if (wid == 0) {
        float winc = wbuf[lane];
        #pragma unroll
        for (int o = 1; o < 32; o <<= 1) {
            float t = __shfl_up_sync(0xffffffffu, winc, o);
            if (lane >= o) winc = fmaxf(winc, t);
        }
        float wex = __shfl_up_sync(0xffffffffu, winc, 1);
        if (lane == 0) wex = -FLT_MAX;
        wbuf[lane] = wex;
    }
    __syncthreads();
    float myex = __shfl_up_sync(0xffffffffu, inc, 1);
    if (lane == 0) myex = -FLT_MAX;
    float pre = fmaxf(wbuf[wid], myex);

    // ex_i = exp(l_i - cummax_i); local running sum
    float m = pre, run = 0.f;
    #pragma unroll
    for (int i = 0; i < 32; i++) {
        m = fmaxf(m, l[i]);
        float e = expf(l[i] - m);
        l[i] = e;
        run += e;
    }
    __syncthreads();

    // block exclusive sum-scan of per-thread totals
    float sinc = run;
    #pragma unroll
    for (int o = 1; o < 32; o <<= 1) {
        float t = __shfl_up_sync(0xffffffffu, sinc, o);
        if (lane >= o) sinc += t;
    }
    if (lane == 31) wbuf[wid] = sinc;
    __syncthreads();
    if (wid == 0) {
        float winc = wbuf[lane];
        #pragma unroll
        for (int o = 1; o < 32; o <<= 1) {
            float t = __shfl_up_sync(0xffffffffu, winc, o);
            if (lane >= o) winc += t;
        }
        float wex = __shfl_up_sync(0xffffffffu, winc, 1);
        if (lane == 0) wex = 0.f;
        wbuf[lane] = wex;
    }
    __syncthreads();
    float sex = __shfl_up_sync(0xffffffffu, sinc, 1);
    if (lane == 0) sex = 0.f;
    float acc = wbuf[wid] + sex;

    float* exg = g_ex   + b * Ln + tid * 32;
    float* psg = g_psum + b * Ln + tid * 32;
    #pragma unroll
    for (int i = 0; i < 32; i++) { acc += l[i]; exg[i] = l[i]; psg[i] = acc; }
}

// ---------------- K3: per-tile partial vector sums ---------------------------
__global__ void k_partial(const float* __restrict__ x) {
    int b = blockIdx.x >> 7, j = blockIdx.x & 127, d = threadIdx.x;   // 128 thr
    __shared__ float se[TILE_T];
    int t0 = j * TILE_T;
    for (int i = d; i < TILE_T; i += 128) se[i] = g_ex[b * Ln + t0 + i];
    __syncthreads();
    float s = 0.f;
    const float* xp = x + ((size_t)(b * Ln + t0)) * Dn + d;
    for (int i = 0; i < TILE_T; i++) s += se[i] * xp[(size_t)i * Dn];
    g_part[(b * NTILES + j) * Dn + d] = s;
}

// ---------------- K4: scan tile partials (exclusive) -------------------------
__global__ void k_scan_part() {
    int b = blockIdx.x, d = threadIdx.x;
    float run = 0.f;
    for (int j = 0; j < NTILES; j++) {
        int idx = (b * NTILES + j) * Dn + d;
        float p = g_part[idx];
        g_part[idx] = run;
        run += p;
    }
}

// ---------------- K5: write prefix_x = cumsum(ex*x)/psum + x -----------------
__global__ void k_prefix(const float* __restrict__ x) {
    int b = blockIdx.x >> 7, j = blockIdx.x & 127, d = threadIdx.x;
    __shared__ float se[TILE_T], sp[TILE_T];
    int t0 = j * TILE_T;
    for (int i = d; i < TILE_T; i += 128) {
        se[i] = g_ex  [b * Ln + t0 + i];
        sp[i] = g_psum[b * Ln + t0 + i];
    }
    __syncthreads();
    float acc = g_part[(b * NTILES + j) * Dn + d];
    const float* xp = x + ((size_t)(b * Ln + t0)) * Dn + d;
    float* op = g_prefix + ((size_t)(b * Ln + t0)) * Dn + d;
    for (int i = 0; i < TILE_T; i++) {
        float xv = xp[(size_t)i * Dn];
        acc += se[i] * xv;
        op[(size_t)i * Dn] = acc / sp[i] + xv;
    }
}

// ---------------- K6: conv as SGEMM (M=512/block tiled 128, N=128, K=768) ----
__global__ __launch_bounds__(256) void k_conv(const float* __restrict__ cb) {
    __shared__ float As[16][132];      // [ci_local][t], padded vs bank conflicts
    __shared__ float Bs[16][128];      // [ci_local][o]
    __shared__ float smax[128];
    int n = blockIdx.x >> 2, mt = blockIdx.x & 3;
    int tid = threadIdx.x;
    int tx = tid & 15, ty = tid >> 4;
    if (tid < 128) smax[tid] = -FLT_MAX;

    float C[8][8] = {};
    int lc = tid & 15;          // A-load ci_local
    int lt = tid >> 4;          // A-load t base
    int bcol = tid & 127;       // B-load col
    int brow = tid >> 7;        // B-load row base
    const float* base = g_prefix + (size_t)n * (BSn * Dn);

    for (int kb = 0; kb < CKn; kb += 16) {
        int k  = kb >> 7;                 // conv tap (chunk never crosses)
        int i0 = kb & 127;
        __syncthreads();
        #pragma unroll
        for (int p = 0; p < 8; p++) {
            int trow = lt + p * 16;
            int r = mt * 128 + trow + k - 2;     // zero pad (2,3)
            float v = 0.f;
            if (r >= 0 && r < BSn) v = base[(size_t)r * Dn + i0 + lc];
            As[lc][trow] = v;
        }
        #pragma unroll
        for (int p = 0; p < 8; p++) {
            int rrow = brow + p * 2;
            Bs[rrow][bcol] = g_Bt[(kb + rrow) * Dn + bcol];
        }
        __syncthreads();
        #pragma unroll
        for (int kk = 0; kk < 16; kk++) {
            float a[8], bb[8];
            #pragma unroll
            for (int i = 0; i < 8; i++) a[i]  = As[kk][ty * 8 + i];
            #pragma unroll
            for (int j = 0; j < 8; j++) bb[j] = Bs[kk][tx * 8 + j];
            #pragma unroll
            for (int i = 0; i < 8; i++)
                #pragma unroll
                for (int j = 0; j < 8; j++)
                    C[i][j] += a[i] * bb[j];
        }
    }
    // epilogue: bias, store conv output, per-channel max -> block_repr
    float* outp = g_conv + ((size_t)n * BSn + mt * 128) * Dn;
    #pragma unroll
    for (int j = 0; j < 8; j++) {
        int col = tx * 8 + j;
        float bias = cb[col];
        float mx = -FLT_MAX;
        #pragma unroll
        for (int i = 0; i < 8; i++) {
            float v = C[i][j] + bias;
            outp[(size_t)(ty * 8 + i) * Dn + col] = v;
            mx = fmaxf(mx, v);
        }
        atomicMaxF(&smax[col], mx);
    }
    __syncthreads();
    if (tid < 128) atomicMaxF(&g_repr[n * Dn + tid], smax[tid]);
}

// ---------------- K7: two attentions + fusion matmul -------------------------
__global__ __launch_bounds__(256) void k_attn(const float* __restrict__ fw,
                                              const float* __restrict__ fb,
                                              float* __restrict__ out, int dup) {
    __shared__ float q[128];
    __shared__ float s[512];
    __shared__ float s2[128];
    __shared__ float fused[384];
    __shared__ float red[8];
    __shared__ float av[2][128];
    int n = blockIdx.x, b = n >> 6, c = n & 63;
    int tid = threadIdx.x, lane = tid & 31, wid = tid >> 5;
    int o = tid & 127, half = tid >> 7;

    if (tid < 128) q[tid] = g_repr[n * 128 + tid];
    __syncthreads();

    // ----- a_s over conv output (512 keys) -----
    const float* cv = g_conv + (size_t)n * BSn * Dn;
    for (int t = wid; t < 512; t += 8) {
        float4 a = ((const float4*)(cv + (size_t)t * Dn))[lane];
        float d = a.x*q[lane*4] + a.y*q[lane*4+1] + a.z*q[lane*4+2] + a.w*q[lane*4+3];
        #pragma unroll
        for (int oo = 16; oo; oo >>= 1) d += __shfl_xor_sync(0xffffffffu, d, oo);
        if (lane == 0) s[t] = d * SCALE_F;
    }
    __syncthreads();
    float m = -FLT_MAX;
    for (int t = tid; t < 512; t += 256) m = fmaxf(m, s[t]);
    m = bredMax(m, red);
    float sum = 0.f;
    for (int t = tid; t < 512; t += 256) { float e = expf(s[t] - m); s[t] = e; sum += e; }
    sum = bredSum(sum, red);
    __syncthreads();
    {
        float acc = 0.f;
        for (int t = half * 256; t < half * 256 + 256; t++)
            acc += s[t] * cv[(size_t)t * Dn + o];
        av[half][o] = acc;
    }
    __syncthreads();
    if (tid < 128) fused[tid] = (av[0][tid] + av[1][tid]) / sum;
    __syncthreads();

    // ----- a_o over boundary-overlap window (128 keys from prefix_x) -----
    const float* px = g_prefix + (size_t)b * Ln * Dn;
    for (int j = wid; j < 128; j += 8) {
        int g = c * 512 + 448 + j; if (g > Ln - 1) g = Ln - 1;   // edge pad
        float4 a = ((const float4*)(px + (size_t)g * Dn))[lane];
        float d = a.x*q[lane*4] + a.y*q[lane*4+1] + a.z*q[lane*4+2] + a.w*q[lane*4+3];
        #pragma unroll
        for (int oo = 16; oo; oo >>= 1) d += __shfl_xor_sync(0xffffffffu, d, oo);
        if (lane == 0) s2[j] = d * SCALE_F;
    }
    __syncthreads();
    float v2 = (tid < 128) ? s2[tid] : -FLT_MAX;
    float m2 = bredMax(v2, red);
    float e2 = (tid < 128) ? expf(s2[tid] - m2) : 0.f;
    if (tid < 128) s2[tid] = e2;
    float sum2 = bredSum(e2, red);
    __syncthreads();
    {
        float acc = 0.f;
        for (int j = half * 64; j < half * 64 + 64; j++) {
            int g = c * 512 + 448 + j; if (g > Ln - 1) g = Ln - 1;
            acc += s2[j] * px[(size_t)g * Dn + o];
        }
        av[half][o] = acc;
    }
    __syncthreads();
    if (tid < 128) {
        fused[128 + tid] = (av[0][tid] + av[1][tid]) / sum2;
        fused[256 + tid] = q[tid];
    }
    __syncthreads();

    // ----- fusion matmul: out[o] = sum_f fused[f] * fw[f*128+o] + fb[o] -----
    {
        float acc = 0.f;
        for (int f = half * 192; f < half * 192 + 192; f++)
            acc += fused[f] * fw[f * Dn + o];
        av[half][o] = acc;
    }
    __syncthreads();
    if (tid < 128) {
        float r = av[0][tid] + av[1][tid] + fb[tid];
        int idx = n * Dn + tid;
        out[idx] = r;
        if (dup) out[NBn * Dn + idx] = r;
    }
}

// ---------------- launch ------------------------------------------------------
extern "C" void kernel_launch(void* const* d_in, const int* in_sizes, int n_in,
                              void* d_out, int out_size) {
    const float* x        = (const float*)d_in[0];
    const float* w_lw     = (const float*)d_in[1];
    const float* b_lw     = (const float*)d_in[2];
    const float* conv_w   = (const float*)d_in[3];
    const float* conv_b   = (const float*)d_in[4];
    const float* fusion_w = (const float*)d_in[5];
    const float* fusion_b = (const float*)d_in[6];
    float* out = (float*)d_out;
    int dup = (out_size >= 2 * NBn * Dn) ? 1 : 0;

    k_prep<<<(CKn * Dn + 255) / 256, 256>>>(conv_w);
    k_init_repr<<<(NBn * Dn + 255) / 256, 256>>>();
    k_logits<<<(Bn * Ln) / 8, 256>>>(x, w_lw, b_lw);
    k_scan_scalar<<<Bn, 1024>>>();
    k_partial<<<Bn * NTILES, 128>>>(x);
    k_scan_part<<<Bn, 128>>>();
    k_prefix<<<Bn * NTILES, 128>>>(x);
    k_conv<<<NBn * 4, 256>>>(conv_b);
    k_attn<<<NBn, 256>>>(fusion_w, fusion_b, out, dup);
}

// round 2
// speedup vs baseline: 2.6098x; 2.6098x over previous
#include <cuda_runtime.h>
#include <math.h>
#include <float.h>

#define Bn   8
#define Ln   32768
#define Dn   128
#define BSn  512
#define BCn  64
#define NBn  512        // B*BC
#define Kc   6
#define CKn  768        // D*K (im2col depth)
#define TILE_T 256
#define NTILES 128      // Ln / TILE_T
#define SCALE_F 0.08838834764831845f  // 1/sqrt(128)

// ---------------- scratch (device globals; no allocations allowed) ----------
__device__ float g_prefix[Bn*Ln*Dn];     // 128 MB
__device__ float g_conv  [NBn*BSn*Dn];   // 128 MB
__device__ float g_logits[Bn*Ln];
__device__ float g_ex    [Bn*Ln];
__device__ float g_psum  [Bn*Ln];
__device__ float g_part  [Bn*NTILES*Dn];
__device__ float g_repr  [NBn*Dn];
__device__ float g_Bt    [CKn*Dn];       // reorganized conv weights [ci][o]

// ---------------- helpers ----------------------------------------------------
__device__ __forceinline__ void atomicMaxF(float* a, float v) {
    if (v >= 0.f) atomicMax((int*)a, __float_as_int(v));
    else          atomicMin((unsigned int*)a, __float_as_uint(v));
}
__device__ __forceinline__ unsigned f2tf32(float f) {
    unsigned r;
    asm("cvt.rna.tf32.f32 %0, %1;" : "=r"(r) : "f"(f));
    return r;
}

// block reduce for 256-thread blocks (8 warps). red: smem float[8].
__device__ __forceinline__ float bredMax(float v, float* red) {
    int lane = threadIdx.x & 31, wid = threadIdx.x >> 5;
    #pragma unroll
    for (int o = 16; o; o >>= 1) v = fmaxf(v, __shfl_xor_sync(0xffffffffu, v, o));
    if (lane == 0) red[wid] = v;
    __syncthreads();
    float r = red[0];
    #pragma unroll
    for (int w = 1; w < 8; w++) r = fmaxf(r, red[w]);
    __syncthreads();
    return r;
}
__device__ __forceinline__ float bredSum(float v, float* red) {
    int lane = threadIdx.x & 31, wid = threadIdx.x >> 5;
    #pragma unroll
    for (int o = 16; o; o >>= 1) v += __shfl_xor_sync(0xffffffffu, v, o);
    if (lane == 0) red[wid] = v;
    __syncthreads();
    float r = red[0];
    #pragma unroll
    for (int w = 1; w < 8; w++) r += red[w];
    __syncthreads();
    return r;
}

// ---------------- K0: weight reorg + repr init -------------------------------
__global__ void k_prep(const float* __restrict__ cw) {
    int idx = blockIdx.x * blockDim.x + threadIdx.x;      // over CKn*Dn
    if (idx >= CKn * Dn) return;
    int ci = idx >> 7, o = idx & 127;
    int k = ci >> 7, i = ci & 127;                         // ci = k*128 + i
    g_Bt[idx] = cw[o * CKn + i * Kc + k];                  // conv_w[o][i][k]
}
__global__ void k_init_repr() {
    int i = blockIdx.x * blockDim.x + threadIdx.x;
    if (i < NBn * Dn) g_repr[i] = -FLT_MAX;
}

// ---------------- K1: logits = silu(x . w + b) -------------------------------
__global__ void k_logits(const float* __restrict__ x, const float* __restrict__ w,
                         const float* __restrict__ b) {
    int tok  = (blockIdx.x * blockDim.x + threadIdx.x) >> 5;
    int lane = threadIdx.x & 31;
    if (tok >= Bn * Ln) return;
    const float4* xr = (const float4*)(x + (size_t)tok * Dn);
    const float4* wr = (const float4*)w;
    float4 a = xr[lane], ww = wr[lane];
    float d = a.x*ww.x + a.y*ww.y + a.z*ww.z + a.w*ww.w;
    #pragma unroll
    for (int o = 16; o; o >>= 1) d += __shfl_xor_sync(0xffffffffu, d, o);
    if (lane == 0) {
        float l = d + b[0];
        g_logits[tok] = l / (1.f + expf(-l));              // silu
    }
}

// ---------------- K2: per-batch scalar scans (cummax -> ex -> cumsum) --------
__global__ __launch_bounds__(1024) void k_scan_scalar() {
    __shared__ float wbuf[32];
    int b = blockIdx.x, tid = threadIdx.x, lane = tid & 31, wid = tid >> 5;
    float4 L4[8];
    const float4* lp4 = (const float4*)(g_logits + b * Ln + tid * 32);
    #pragma unroll
    for (int i = 0; i < 8; i++) L4[i] = lp4[i];
    float* l = (float*)L4;
    float tmax = -FLT_MAX;
    #pragma unroll
    for (int i = 0; i < 32; i++) tmax = fmaxf(tmax, l[i]);

    // block exclusive max-scan of per-thread maxima
    float inc = tmax;
    #pragma unroll
    for (int o = 1; o < 32; o <<= 1) {
        float t = __shfl_up_sync(0xffffffffu, inc, o);
        if (lane >= o) inc = fmaxf(inc, t);
    }
    if (lane == 31) wbuf[wid] = inc;
    __syncthreads();
    if (wid == 0) {
        float winc = wbuf[lane];
        #pragma unroll
        for (int o = 1; o < 32; o <<= 1) {
            float t = __shfl_up_sync(0xffffffffu, winc, o);
            if (lane >= o) winc += 0.f, winc = fmaxf(winc, t);
        }
        float wex = __shfl_up_sync(0xffffffffu, winc, 1);
        if (lane == 0) wex = -FLT_MAX;
        wbuf[lane] = wex;
    }
    __syncthreads();
    float myex = __shfl_up_sync(0xffffffffu, inc, 1);
    if (lane == 0) myex = -FLT_MAX;
    float pre = fmaxf(wbuf[wid], myex);

    // ex_i = exp(l_i - cummax_i); local running sum
    float m = pre, run = 0.f;
    #pragma unroll
    for (int i = 0; i < 32; i++) {
        m = fmaxf(m, l[i]);
        float e = expf(l[i] - m);
        l[i] = e;
        run += e;
    }
    __syncthreads();

    // block exclusive sum-scan of per-thread totals
    float sinc = run;
    #pragma unroll
    for (int o = 1; o < 32; o <<= 1) {
        float t = __shfl_up_sync(0xffffffffu, sinc, o);
        if (lane >= o) sinc += t;
    }
    if (lane == 31) wbuf[wid] = sinc;
    __syncthreads();
    if (wid == 0) {
        float winc = wbuf[lane];
        #pragma unroll
        for (int o = 1; o < 32; o <<= 1) {
            float t = __shfl_up_sync(0xffffffffu, winc, o);
            if (lane >= o) winc += t;
        }
        float wex = __shfl_up_sync(0xffffffffu, winc, 1);
        if (lane == 0) wex = 0.f;
        wbuf[lane] = wex;
    }
    __syncthreads();
    float sex = __shfl_up_sync(0xffffffffu, sinc, 1);
    if (lane == 0) sex = 0.f;
    float acc = wbuf[wid] + sex;

    float4* exg = (float4*)(g_ex   + b * Ln + tid * 32);
    float4* psg = (float4*)(g_psum + b * Ln + tid * 32);
    #pragma unroll
    for (int i = 0; i < 8; i++) {
        float4 ps;
        acc += l[i*4+0]; ps.x = acc;
        acc += l[i*4+1]; ps.y = acc;
        acc += l[i*4+2]; ps.z = acc;
        acc += l[i*4+3]; ps.w = acc;
        exg[i] = L4[i];
        psg[i] = ps;
    }
}

// ---------------- K3: per-tile partial vector sums ---------------------------
__global__ void k_partial(const float* __restrict__ x) {
    int b = blockIdx.x >> 7, j = blockIdx.x & 127, d = threadIdx.x;   // 128 thr
    __shared__ float se[TILE_T];
    int t0 = j * TILE_T;
    for (int i = d; i < TILE_T; i += 128) se[i] = g_ex[b * Ln + t0 + i];
    __syncthreads();
    float s = 0.f;
    const float* xp = x + ((size_t)(b * Ln + t0)) * Dn + d;
    for (int i = 0; i < TILE_T; i++) s += se[i] * xp[(size_t)i * Dn];
    g_part[(b * NTILES + j) * Dn + d] = s;
}

// ---------------- K4: scan tile partials (exclusive) -------------------------
__global__ void k_scan_part() {
    int b = blockIdx.x, d = threadIdx.x;
    float run = 0.f;
    for (int j = 0; j < NTILES; j++) {
        int idx = (b * NTILES + j) * Dn + d;
        float p = g_part[idx];
        g_part[idx] = run;
        run += p;
    }
}

// ---------------- K5: write prefix_x = cumsum(ex*x)/psum + x -----------------
__global__ void k_prefix(const float* __restrict__ x) {
    int b = blockIdx.x >> 7, j = blockIdx.x & 127, d = threadIdx.x;
    __shared__ float se[TILE_T], sp[TILE_T];
    int t0 = j * TILE_T;
    for (int i = d; i < TILE_T; i += 128) {
        se[i] = g_ex  [b * Ln + t0 + i];
        sp[i] = g_psum[b * Ln + t0 + i];
    }
    __syncthreads();
    float acc = g_part[(b * NTILES + j) * Dn + d];
    const float* xp = x + ((size_t)(b * Ln + t0)) * Dn + d;
    float* op = g_prefix + ((size_t)(b * Ln + t0)) * Dn + d;
    for (int i = 0; i < TILE_T; i++) {
        float xv = xp[(size_t)i * Dn];
        acc += se[i] * xv;
        op[(size_t)i * Dn] = acc / sp[i] + xv;
    }
}

// ---------------- K6: conv as tf32 tensor-core GEMM --------------------------
// Per block: 128 t-rows x 128 out-channels, K=768 (6 taps x 128 in-channels).
// A slab (133 rows x 128 ch, tf32) loaded to smem ONCE; taps = row offsets.
// B chunk (64 x 128, tf32) staged per K-chunk.
#define SA 132          // slab row stride (floats) — conflict-free A frags
#define SB 136          // Bs   row stride (floats) — conflict-free B frags
#define KCH 64          // K chunk

__global__ __launch_bounds__(256) void k_conv2(const float* __restrict__ cb) {
    extern __shared__ unsigned sh[];
    unsigned* slab = sh;                       // 133*SA tf32
    unsigned* Bs   = sh + 133 * SA;            // KCH*SB tf32
    float*    smax = (float*)(Bs + KCH * SB);  // 128 floats

    int n = blockIdx.x >> 2, mt = blockIdx.x & 3;
    int tid = threadIdx.x;
    int warp = tid >> 5, lane = tid & 31;
    int wm = warp & 1, wn = warp >> 1;         // warp tile: 64 rows x 32 cols
    int tq = lane >> 2, cq = lane & 3;

    if (tid < 128) smax[tid] = -FLT_MAX;

    // ---- load A slab: rows r = mt*128 - 2 .. mt*128 + 130 (zero-padded) ----
    {
        const float* base = g_prefix + (size_t)n * (BSn * Dn);
        int t0 = mt * 128 - 2;
        for (int idx = tid; idx < 133 * 32; idx += 256) {
            int srow = idx >> 5, c4 = idx & 31;
            int r = t0 + srow;
            float4 v = make_float4(0.f, 0.f, 0.f, 0.f);
            if (r >= 0 && r < BSn)
                v = *(const float4*)(base + (size_t)r * Dn + c4 * 4);
            unsigned* dst = slab + srow * SA + c4 * 4;
            dst[0] = f2tf32(v.x); dst[1] = f2tf32(v.y);
            dst[2] = f2tf32(v.z); dst[3] = f2tf32(v.w);
        }
    }

    float c[4][4][4];
    #pragma unroll
    for (int i = 0; i < 4; i++)
        #pragma unroll
        for (int j = 0; j < 4; j++)
            #pragma unroll
            for (int r = 0; r < 4; r++) c[i][j][r] = 0.f;

    for (int kb = 0; kb < CKn; kb += KCH) {
        int tap = kb >> 7;                 // chunk never crosses tap boundary
        int i0  = kb & 127;
        __syncthreads();
        // stage B chunk
        for (int idx = tid; idx < KCH * 32; idx += 256) {
            int row = idx >> 5, c4 = idx & 31;
            const float4 v = *(const float4*)(g_Bt + (size_t)(kb + row) * Dn + c4 * 4);
            unsigned* dst = Bs + row * SB + c4 * 4;
            dst[0] = f2tf32(v.x); dst[1] = f2tf32(v.y);
            dst[2] = f2tf32(v.z); dst[3] = f2tf32(v.w);
        }
        __syncthreads();

        #pragma unroll
        for (int ks = 0; ks < KCH; ks += 8) {
            // A fragments: 4 m-tiles of 16 rows
            unsigned a[4][4];
            #pragma unroll
            for (int mi = 0; mi < 4; mi++) {
                int rb = wm * 64 + mi * 16 + tq + tap;   // slab row (t + tap)
                int cc = i0 + ks + cq;
                a[mi][0] = slab[rb * SA + cc];
                a[mi][1] = slab[(rb + 8) * SA + cc];
                a[mi][2] = slab[rb * SA + cc + 4];
                a[mi][3] = slab[(rb + 8) * SA + cc + 4];
            }
            // B fragments: 4 n-tiles of 8 cols
            unsigned bfr[4][2];
            #pragma unroll
            for (int ni = 0; ni < 4; ni++) {
                int col = wn * 32 + ni * 8 + tq;
                bfr[ni][0] = Bs[(ks + cq) * SB + col];
                bfr[ni][1] = Bs[(ks + cq + 4) * SB + col];
            }
            #pragma unroll
            for (int mi = 0; mi < 4; mi++)
                #pragma unroll
                for (int ni = 0; ni < 4; ni++) {
                    asm volatile(
                        "mma.sync.aligned.m16n8k8.row.col.f32.tf32.tf32.f32 "
                        "{%0,%1,%2,%3}, {%4,%5,%6,%7}, {%8,%9}, {%0,%1,%2,%3};"
                        : "+f"(c[mi][ni][0]), "+f"(c[mi][ni][1]),
                          "+f"(c[mi][ni][2]), "+f"(c[mi][ni][3])
                        : "r"(a[mi][0]), "r"(a[mi][1]), "r"(a[mi][2]), "r"(a[mi][3]),
                          "r"(bfr[ni][0]), "r"(bfr[ni][1]));
                }
        }
    }

    // ---- epilogue: bias, store conv output, per-channel running max --------
    float* outp = g_conv + ((size_t)n * BSn + mt * 128) * Dn;
    #pragma unroll
    for (int ni = 0; ni < 4; ni++) {
        int col = wn * 32 + ni * 8 + 2 * cq;
        float b0 = cb[col], b1 = cb[col + 1];
        float mx0 = -FLT_MAX, mx1 = -FLT_MAX;
        #pragma unroll
        for (int mi = 0; mi < 4; mi++) {
            int row = wm * 64 + mi * 16 + tq;
            float v0 = c[mi][ni][0] + b0, v1 = c[mi][ni][1] + b1;
            float v2 = c[mi][ni][2] + b0, v3 = c[mi][ni][3] + b1;
            *(float2*)(outp + (size_t)row * Dn + col)       = make_float2(v0, v1);
            *(float2*)(outp + (size_t)(row + 8) * Dn + col) = make_float2(v2, v3);
            mx0 = fmaxf(mx0, fmaxf(v0, v2));
            mx1 = fmaxf(mx1, fmaxf(v1, v3));
        }
        atomicMaxF(&smax[col], mx0);
        atomicMaxF(&smax[col + 1], mx1);
    }
    __syncthreads();
    if (tid < 128) atomicMaxF(&g_repr[n * Dn + tid], smax[tid]);
}

// ---------------- K7: two attentions + fusion matmul -------------------------
__global__ __launch_bounds__(256) void k_attn(const float* __restrict__ fw,
                                              const float* __restrict__ fb,
                                              float* __restrict__ out, int dup) {
    __shared__ float q[128];
    __shared__ float s[512];
    __shared__ float s2[128];
    __shared__ float fused[384];
    __shared__ float red[8];
    __shared__ float av[2][128];
    int n = blockIdx.x, b = n >> 6, c = n & 63;
    int tid = threadIdx.x, lane = tid & 31, wid = tid >> 5;
    int o = tid & 127, half = tid >> 7;

    if (tid < 128) q[tid] = g_repr[n * 128 + tid];
    __syncthreads();

    // ----- a_s over conv output (512 keys) -----
    const float* cv = g_conv + (size_t)n * BSn * Dn;
    for (int t = wid; t < 512; t += 8) {
        float4 a = ((const float4*)(cv + (size_t)t * Dn))[lane];
        float d = a.x*q[lane*4] + a.y*q[lane*4+1] + a.z*q[lane*4+2] + a.w*q[lane*4+3];
        #pragma unroll
        for (int oo = 16; oo; oo >>= 1) d += __shfl_xor_sync(0xffffffffu, d, oo);
        if (lane == 0) s[t] = d * SCALE_F;
    }
    __syncthreads();
    float m = -FLT_MAX;
    for (int t = tid; t < 512; t += 256) m = fmaxf(m, s[t]);
    m = bredMax(m, red);
    float sum = 0.f;
    for (int t = tid; t < 512; t += 256) { float e = expf(s[t] - m); s[t] = e; sum += e; }
    sum = bredSum(sum, red);
    __syncthreads();
    {
        float acc = 0.f;
        for (int t = half * 256; t < half * 256 + 256; t++)
            acc += s[t] * cv[(size_t)t * Dn + o];
        av[half][o] = acc;
    }
    __syncthreads();
    if (tid < 128) fused[tid] = (av[0][tid] + av[1][tid]) / sum;
    __syncthreads();

    // ----- a_o over boundary-overlap window (128 keys from prefix_x) -----
    const float* px = g_prefix + (size_t)b * Ln * Dn;
    for (int j = wid; j < 128; j += 8) {
        int g = c * 512 + 448 + j; if (g > Ln - 1) g = Ln - 1;   // edge pad
        float4 a = ((const float4*)(px + (size_t)g * Dn))[lane];
        float d = a.x*q[lane*4] + a.y*q[lane*4+1] + a.z*q[lane*4+2] + a.w*q[lane*4+3];
        #pragma unroll
        for (int oo = 16; oo; oo >>= 1) d += __shfl_xor_sync(0xffffffffu, d, oo);
        if (lane == 0) s2[j] = d * SCALE_F;
    }
    __syncthreads();
    float v2 = (tid < 128) ? s2[tid] : -FLT_MAX;
    float m2 = bredMax(v2, red);
    float e2 = (tid < 128) ? expf(s2[tid] - m2) : 0.f;
    if (tid < 128) s2[tid] = e2;
    float sum2 = bredSum(e2, red);
    __syncthreads();
    {
        float acc = 0.f;
        for (int j = half * 64; j < half * 64 + 64; j++) {
            int g = c * 512 + 448 + j; if (g > Ln - 1) g = Ln - 1;
            acc += s2[j] * px[(size_t)g * Dn + o];
        }
        av[half][o] = acc;
    }
    __syncthreads();
    if (tid < 128) {
        fused[128 + tid] = (av[0][tid] + av[1][tid]) / sum2;
        fused[256 + tid] = q[tid];
    }
    __syncthreads();

    // ----- fusion matmul: out[o] = sum_f fused[f] * fw[f*128+o] + fb[o] -----
    {
        float acc = 0.f;
        for (int f = half * 192; f < half * 192 + 192; f++)
            acc += fused[f] * fw[f * Dn + o];
        av[half][o] = acc;
    }
    __syncthreads();
    if (tid < 128) {
        float r = av[0][tid] + av[1][tid] + fb[tid];
        int idx = n * Dn + tid;
        out[idx] = r;
        if (dup) out[NBn * Dn + idx] = r;
    }
}

// ---------------- launch ------------------------------------------------------
extern "C" void kernel_launch(void* const* d_in, const int* in_sizes, int n_in,
                              void* d_out, int out_size) {
    const float* x        = (const float*)d_in[0];
    const float* w_lw     = (const float*)d_in[1];
    const float* b_lw     = (const float*)d_in[2];
    const float* conv_w   = (const float*)d_in[3];
    const float* conv_b   = (const float*)d_in[4];
    const float* fusion_w = (const float*)d_in[5];
    const float* fusion_b = (const float*)d_in[6];
    float* out = (float*)d_out;
    int dup = (out_size >= 2 * NBn * Dn) ? 1 : 0;

    int convSmem = (133 * SA + KCH * SB) * 4 + 128 * 4;
    cudaFuncSetAttribute(k_conv2, cudaFuncAttributeMaxDynamicSharedMemorySize, convSmem);

    k_prep<<<(CKn * Dn + 255) / 256, 256>>>(conv_w);
    k_init_repr<<<(NBn * Dn + 255) / 256, 256>>>();
    k_logits<<<(Bn * Ln) / 8, 256>>>(x, w_lw, b_lw);
    k_scan_scalar<<<Bn, 1024>>>();
    k_partial<<<Bn * NTILES, 128>>>(x);
    k_scan_part<<<Bn, 128>>>();
    k_prefix<<<Bn * NTILES, 128>>>(x);
    k_conv2<<<NBn * 4, 256, convSmem>>>(conv_b);
    k_attn<<<NBn, 256>>>(fusion_w, fusion_b, out, dup);
}

// round 4
// speedup vs baseline: 3.9144x; 1.4999x over previous
#include <cuda_runtime.h>
#include <cuda_fp16.h>
#include <math.h>
#include <float.h>
#include <stdint.h>

#define Bn   8
#define Ln   32768
#define Dn   128
#define BSn  512
#define BCn  64
#define NBn  512        // B*BC
#define Kc   6
#define TILE_T 256
#define NTILES 128      // Ln / TILE_T
#define SCALE_F 0.08838834764831845f  // 1/sqrt(128)

// ---------------- scratch (device globals; no allocations allowed) ----------
__device__ __align__(256) __half g_prefixh[Bn*Ln*Dn];   // 64 MB, fp16
__device__ __align__(256) float  g_conv  [NBn*BSn*Dn];  // 128 MB
__device__ float g_logits[Bn*Ln];
__device__ float g_ex    [Bn*Ln];
__device__ float g_psum  [Bn*Ln];
__device__ float g_part  [Bn*NTILES*Dn];
__device__ float g_repr  [NBn*Dn];
__device__ __align__(256) __half g_Bth[Kc*Dn*Dn];       // [tap][o][i] fp16

// ---------------- helpers ----------------------------------------------------
__device__ __forceinline__ void atomicMaxF(float* a, float v) {
    if (v >= 0.f) atomicMax((int*)a, __float_as_int(v));
    else          atomicMin((unsigned int*)a, __float_as_uint(v));
}
__device__ __forceinline__ uint32_t smem_u32(const void* p) {
    uint32_t a;
    asm("{ .reg .u64 t; cvta.to.shared.u64 t, %1; cvt.u32.u64 %0, t; }" : "=r"(a) : "l"(p));
    return a;
}
__device__ __forceinline__ void cpasync16(uint32_t dst, const void* src, int sz) {
    asm volatile("cp.async.cg.shared.global [%0], [%1], 16, %2;"
                 :: "r"(dst), "l"(src), "r"(sz) : "memory");
}
// fp16 smem tile: rows of 256B (128 halves), XOR swizzle; c = 16B chunk [0,16)
__device__ __forceinline__ uint32_t swzh(int row, int c) {
    return ((uint32_t)row << 8) + ((uint32_t)((c & 8) | ((c ^ row) & 7)) << 4);
}

// block reduce for 256-thread blocks (8 warps). red: smem float[8].
__device__ __forceinline__ float bredMax(float v, float* red) {
    int lane = threadIdx.x & 31, wid = threadIdx.x >> 5;
    #pragma unroll
    for (int o = 16; o; o >>= 1) v = fmaxf(v, __shfl_xor_sync(0xffffffffu, v, o));
    if (lane == 0) red[wid] = v;
    __syncthreads();
    float r = red[0];
    #pragma unroll
    for (int w = 1; w < 8; w++) r = fmaxf(r, red[w]);
    __syncthreads();
    return r;
}
__device__ __forceinline__ float bredSum(float v, float* red) {
    int lane = threadIdx.x & 31, wid = threadIdx.x >> 5;
    #pragma unroll
    for (int o = 16; o; o >>= 1) v += __shfl_xor_sync(0xffffffffu, v, o);
    if (lane == 0) red[wid] = v;
    __syncthreads();
    float r = red[0];
    #pragma unroll
    for (int w = 1; w < 8; w++) r += red[w];
    __syncthreads();
    return r;
}

// ---------------- K0: weight reorg to [tap][o][i] fp16; repr init ------------
__global__ void k_prep(const float* __restrict__ cw) {
    int idx = blockIdx.x * blockDim.x + threadIdx.x;      // over 6*128*128
    if (idx >= Kc * Dn * Dn) return;
    int tap = idx >> 14, o = (idx >> 7) & 127, i = idx & 127;
    g_Bth[idx] = __float2half_rn(cw[o * (Dn * Kc) + i * Kc + tap]);
}
__global__ void k_init_repr() {
    int i = blockIdx.x * blockDim.x + threadIdx.x;
    if (i < NBn * Dn) g_repr[i] = -FLT_MAX;
}

// ---------------- K1: logits = silu(x . w + b) -------------------------------
__global__ void k_logits(const float* __restrict__ x, const float* __restrict__ w,
                         const float* __restrict__ b) {
    int tok  = (blockIdx.x * blockDim.x + threadIdx.x) >> 5;
    int lane = threadIdx.x & 31;
    if (tok >= Bn * Ln) return;
    const float4* xr = (const float4*)(x + (size_t)tok * Dn);
    const float4* wr = (const float4*)w;
    float4 a = xr[lane], ww = wr[lane];
    float d = a.x*ww.x + a.y*ww.y + a.z*ww.z + a.w*ww.w;
    #pragma unroll
    for (int o = 16; o; o >>= 1) d += __shfl_xor_sync(0xffffffffu, d, o);
    if (lane == 0) {
        float l = d + b[0];
        g_logits[tok] = l / (1.f + expf(-l));              // silu
    }
}

// ---------------- K2: per-batch scalar scans (cummax -> ex -> cumsum) --------
__global__ __launch_bounds__(1024) void k_scan_scalar() {
    __shared__ float wbuf[32];
    int b = blockIdx.x, tid = threadIdx.x, lane = tid & 31, wid = tid >> 5;
    float4 L4[8];
    const float4* lp4 = (const float4*)(g_logits + b * Ln + tid * 32);
    #pragma unroll
    for (int i = 0; i < 8; i++) L4[i] = lp4[i];
    float* l = (float*)L4;
    float tmax = -FLT_MAX;
    #pragma unroll
    for (int i = 0; i < 32; i++) tmax = fmaxf(tmax, l[i]);

    float inc = tmax;
    #pragma unroll
    for (int o = 1; o < 32; o <<= 1) {
        float t = __shfl_up_sync(0xffffffffu, inc, o);
        if (lane >= o) inc = fmaxf(inc, t);
    }
    if (lane == 31) wbuf[wid] = inc;
    __syncthreads();
    if (wid == 0) {
        float winc = wbuf[lane];
        #pragma unroll
        for (int o = 1; o < 32; o <<= 1) {
            float t = __shfl_up_sync(0xffffffffu, winc, o);
            if (lane >= o) winc = fmaxf(winc, t);
        }
        float wex = __shfl_up_sync(0xffffffffu, winc, 1);
        if (lane == 0) wex = -FLT_MAX;
        wbuf[lane] = wex;
    }
    __syncthreads();
    float myex = __shfl_up_sync(0xffffffffu, inc, 1);
    if (lane == 0) myex = -FLT_MAX;
    float pre = fmaxf(wbuf[wid], myex);

    float m = pre, run = 0.f;
    #pragma unroll
    for (int i = 0; i < 32; i++) {
        m = fmaxf(m, l[i]);
        float e = expf(l[i] - m);
        l[i] = e;
        run += e;
    }
    __syncthreads();

    float sinc = run;
    #pragma unroll
    for (int o = 1; o < 32; o <<= 1) {
        float t = __shfl_up_sync(0xffffffffu, sinc, o);
        if (lane >= o) sinc += t;
    }
    if (lane == 31) wbuf[wid] = sinc;
    __syncthreads();
    if (wid == 0) {
        float winc = wbuf[lane];
        #pragma unroll
        for (int o = 1; o < 32; o <<= 1) {
            float t = __shfl_up_sync(0xffffffffu, winc, o);
            if (lane >= o) winc += t;
        }
        float wex = __shfl_up_sync(0xffffffffu, winc, 1);
        if (lane == 0) wex = 0.f;
        wbuf[lane] = wex;
    }
    __syncthreads();
    float sex = __shfl_up_sync(0xffffffffu, sinc, 1);
    if (lane == 0) sex = 0.f;
    float acc = wbuf[wid] + sex;

    float4* exg = (float4*)(g_ex   + b * Ln + tid * 32);
    float4* psg = (float4*)(g_psum + b * Ln + tid * 32);
    #pragma unroll
    for (int i = 0; i < 8; i++) {
        float4 ps;
        acc += l[i*4+0]; ps.x = acc;
        acc += l[i*4+1]; ps.y = acc;
        acc += l[i*4+2]; ps.z = acc;
        acc += l[i*4+3]; ps.w = acc;
        exg[i] = L4[i];
        psg[i] = ps;
    }
}

// ---------------- K3: per-tile partial vector sums ---------------------------
__global__ void k_partial(const float* __restrict__ x) {
    int b = blockIdx.x >> 7, j = blockIdx.x & 127, d = threadIdx.x;   // 128 thr
    __shared__ float se[TILE_T];
    int t0 = j * TILE_T;
    for (int i = d; i < TILE_T; i += 128) se[i] = g_ex[b * Ln + t0 + i];
    __syncthreads();
    float s = 0.f;
    const float* xp = x + ((size_t)(b * Ln + t0)) * Dn + d;
    for (int i = 0; i < TILE_T; i++) s += se[i] * xp[(size_t)i * Dn];
    g_part[(b * NTILES + j) * Dn + d] = s;
}

// ---------------- K4: scan tile partials (exclusive) -------------------------
__global__ void k_scan_part() {
    int b = blockIdx.x, d = threadIdx.x;
    float run = 0.f;
    for (int j = 0; j < NTILES; j++) {
        int idx = (b * NTILES + j) * Dn + d;
        float p = g_part[idx];
        g_part[idx] = run;
        run += p;
    }
}

// ---------------- K5: prefix_x = cumsum(ex*x)/psum + x -> fp16 ---------------
__global__ void k_prefix(const float* __restrict__ x) {
    int b = blockIdx.x >> 7, j = blockIdx.x & 127, d = threadIdx.x;
    __shared__ float se[TILE_T], sp[TILE_T];
    int t0 = j * TILE_T;
    for (int i = d; i < TILE_T; i += 128) {
        se[i] = g_ex  [b * Ln + t0 + i];
        sp[i] = g_psum[b * Ln + t0 + i];
    }
    __syncthreads();
    float acc = g_part[(b * NTILES + j) * Dn + d];
    const float* xp = x + ((size_t)(b * Ln + t0)) * Dn + d;
    __half* op = g_prefixh + ((size_t)(b * Ln + t0)) * Dn + d;
    for (int i = 0; i < TILE_T; i++) {
        float xv = xp[(size_t)i * Dn];
        acc += se[i] * xv;
        op[(size_t)i * Dn] = __float2half_rn(acc / sp[i] + xv);
    }
}

// ---------------- K6: conv as fp16 HMMA GEMM ---------------------------------
// CTA: 128 t-rows x 128 out-ch, K=768. A slab (133x128 fp16) loaded ONCE;
// per-tap B (128x128 fp16) double-buffered via cp.async. ldmatrix.x4 frags.
#define CONV_SMEM (34048 + 2*32768 + 512)
__global__ __launch_bounds__(256) void k_conv_h(const float* __restrict__ cb) {
    extern __shared__ __align__(256) char sh[];
    uint32_t aA = smem_u32(sh);                  // 133 rows x 256B swizzled
    uint32_t aB = aA + 34048;                    // 2 stages x 32KB
    float* smax = (float*)(sh + 34048 + 65536);  // 128 floats

    int n = blockIdx.x >> 2, mt = blockIdx.x & 3;
    int tid = threadIdx.x, warp = tid >> 5, lane = tid & 31;
    int wm = warp >> 2, wn = warp & 3;           // warp tile 64 x 32
    int grp = lane >> 3;

    if (tid < 128) smax[tid] = -FLT_MAX;

    // A slab: rows t0-2 .. t0+130 (zero-padded outside block)
    {
        const __half* base = g_prefixh + (size_t)n * (BSn * Dn);
        int t0 = mt * 128 - 2;
        #pragma unroll
        for (int i = 0; i < 9; i++) {
            int lin = tid + 256 * i;
            if (lin < 133 * 16) {
                int row = lin >> 4, c = lin & 15;
                int rg = t0 + row;
                int ok = (rg >= 0 && rg < BSn);
                cpasync16(aA + swzh(row, c),
                          base + (size_t)(ok ? rg : 0) * Dn + c * 8, ok ? 16 : 0);
            }
        }
    }
    // B tap 0 -> buf 0
    {
        const __half* bt = g_Bth;
        #pragma unroll
        for (int i = 0; i < 8; i++) {
            int lin = tid + 256 * i;
            int row = lin >> 4, c = lin & 15;
            cpasync16(aB + swzh(row, c), bt + row * Dn + c * 8, 16);
        }
    }
    asm volatile("cp.async.commit_group;" ::: "memory");

    float C[4][4][4];
    #pragma unroll
    for (int a = 0; a < 4; a++)
        #pragma unroll
        for (int b = 0; b < 4; b++)
            #pragma unroll
            for (int r = 0; r < 4; r++) C[a][b][r] = 0.f;

    for (int tap = 0; tap < 6; tap++) {
        if (tap < 5) {
            uint32_t dst = aB + ((tap + 1) & 1) * 32768;
            const __half* bt = g_Bth + (size_t)(tap + 1) * Dn * Dn;
            #pragma unroll
            for (int i = 0; i < 8; i++) {
                int lin = tid + 256 * i;
                int row = lin >> 4, c = lin & 15;
                cpasync16(dst + swzh(row, c), bt + row * Dn + c * 8, 16);
            }
            asm volatile("cp.async.commit_group;" ::: "memory");
            asm volatile("cp.async.wait_group 1;" ::: "memory");
        } else {
            asm volatile("cp.async.wait_group 0;" ::: "memory");
        }
        __syncthreads();
        uint32_t bufB = aB + (tap & 1) * 32768;

        #pragma unroll
        for (int ks = 0; ks < 8; ks++) {
            int c0 = ks * 2;
            uint32_t af[4][4];
            #pragma unroll
            for (int mi = 0; mi < 4; mi++) {
                int row = wm * 64 + mi * 16 + tap + ((grp & 1) << 3) + (lane & 7);
                uint32_t ad = aA + swzh(row, c0 + (grp >> 1));
                asm volatile("ldmatrix.sync.aligned.m8n8.x4.shared.b16 {%0,%1,%2,%3}, [%4];"
                    : "=r"(af[mi][0]), "=r"(af[mi][1]), "=r"(af[mi][2]), "=r"(af[mi][3])
                    : "r"(ad));
            }
            uint32_t bf[2][4];
            #pragma unroll
            for (int pr = 0; pr < 2; pr++) {
                int row = wn * 32 + pr * 16 + ((grp >> 1) << 3) + (lane & 7);
                uint32_t ad = bufB + swzh(row, c0 + (grp & 1));
                asm volatile("ldmatrix.sync.aligned.m8n8.x4.shared.b16 {%0,%1,%2,%3}, [%4];"
                    : "=r"(bf[pr][0]), "=r"(bf[pr][1]), "=r"(bf[pr][2]), "=r"(bf[pr][3])
                    : "r"(ad));
            }
            #pragma unroll
            for (int mi = 0; mi < 4; mi++)
                #pragma unroll
                for (int pr = 0; pr < 2; pr++) {
                    asm volatile(
                        "mma.sync.aligned.m16n8k16.row.col.f32.f16.f16.f32 "
                        "{%0,%1,%2,%3}, {%4,%5,%6,%7}, {%8,%9}, {%0,%1,%2,%3};"
                        : "+f"(C[mi][2*pr][0]), "+f"(C[mi][2*pr][1]),
                          "+f"(C[mi][2*pr][2]), "+f"(C[mi][2*pr][3])
                        : "r"(af[mi][0]), "r"(af[mi][1]), "r"(af[mi][2]), "r"(af[mi][3]),
                          "r"(bf[pr][0]), "r"(bf[pr][1]));
                    asm volatile(
                        "mma.sync.aligned.m16n8k16.row.col.f32.f16.f16.f32 "
                        "{%0,%1,%2,%3}, {%4,%5,%6,%7}, {%8,%9}, {%0,%1,%2,%3};"
                        : "+f"(C[mi][2*pr+1][0]), "+f"(C[mi][2*pr+1][1]),
                          "+f"(C[mi][2*pr+1][2]), "+f"(C[mi][2*pr+1][3])
                        : "r"(af[mi][0]), "r"(af[mi][1]), "r"(af[mi][2]), "r"(af[mi][3]),
                          "r"(bf[pr][2]), "r"(bf[pr][3]));
                }
        }
        __syncthreads();
    }

    // epilogue: bias, store conv, per-channel max
    float* outp = g_conv + ((size_t)n * BSn + mt * 128) * Dn;
    #pragma unroll
    for (int ni = 0; ni < 4; ni++) {
        int col = wn * 32 + ni * 8 + (lane & 3) * 2;
        float b0 = cb[col], b1 = cb[col + 1];
        float mx0 = -FLT_MAX, mx1 = -FLT_MAX;
        #pragma unroll
        for (int mi = 0; mi < 4; mi++) {
            int row = wm * 64 + mi * 16 + (lane >> 2);
            float v0 = C[mi][ni][0] + b0, v1 = C[mi][ni][1] + b1;
            float v2 = C[mi][ni][2] + b0, v3 = C[mi][ni][3] + b1;
            *(float2*)(outp + (size_t)row * Dn + col)       = make_float2(v0, v1);
            *(float2*)(outp + (size_t)(row + 8) * Dn + col) = make_float2(v2, v3);
            mx0 = fmaxf(mx0, fmaxf(v0, v2));
            mx1 = fmaxf(mx1, fmaxf(v1, v3));
        }
        atomicMaxF(&smax[col], mx0);
        atomicMaxF(&smax[col + 1], mx1);
    }
    __syncthreads();
    if (tid < 128) atomicMaxF(&g_repr[n * Dn + tid], smax[tid]);
}

// ---------------- K7: two attentions + fusion matmul -------------------------
__global__ __launch_bounds__(256) void k_attn(const float* __restrict__ fw,
                                              const float* __restrict__ fb,
                                              float* __restrict__ out, int dup) {
    __shared__ float q[128];
    __shared__ float s[512];
    __shared__ float s2[128];
    __shared__ float fused[384];
    __shared__ float red[8];
    __shared__ float av[2][128];
    int n = blockIdx.x, b = n >> 6, c = n & 63;
    int tid = threadIdx.x, lane = tid & 31, wid = tid >> 5;
    int o = tid & 127, half = tid >> 7;

    if (tid < 128) q[tid] = g_repr[n * 128 + tid];
    __syncthreads();

    const float* cv = g_conv + (size_t)n * BSn * Dn;
    for (int t = wid; t < 512; t += 8) {
        float4 a = ((const float4*)(cv + (size_t)t * Dn))[lane];
        float d = a.x*q[lane*4] + a.y*q[lane*4+1] + a.z*q[lane*4+2] + a.w*q[lane*4+3];
        #pragma unroll
        for (int oo = 16; oo; oo >>= 1) d += __shfl_xor_sync(0xffffffffu, d, oo);
        if (lane == 0) s[t] = d * SCALE_F;
    }
    __syncthreads();
    float m = -FLT_MAX;
    for (int t = tid; t < 512; t += 256) m = fmaxf(m, s[t]);
    m = bredMax(m, red);
    float sum = 0.f;
    for (int t = tid; t < 512; t += 256) { float e = expf(s[t] - m); s[t] = e; sum += e; }
    sum = bredSum(sum, red);
    __syncthreads();
    {
        float acc = 0.f;
        for (int t = half * 256; t < half * 256 + 256; t++)
            acc += s[t] * cv[(size_t)t * Dn + o];
        av[half][o] = acc;
    }
    __syncthreads();
    if (tid < 128) fused[tid] = (av[0][tid] + av[1][tid]) / sum;
    __syncthreads();

    const __half* px = g_prefixh + (size_t)b * Ln * Dn;
    for (int j = wid; j < 128; j += 8) {
        int g = c * 512 + 448 + j; if (g > Ln - 1) g = Ln - 1;   // edge pad
        const __half2* r = (const __half2*)(px + (size_t)g * Dn) + lane * 2;
        __half2 h0 = r[0], h1 = r[1];
        float d = __low2float(h0)*q[lane*4]   + __high2float(h0)*q[lane*4+1]
                + __low2float(h1)*q[lane*4+2] + __high2float(h1)*q[lane*4+3];
        #pragma unroll
        for (int oo = 16; oo; oo >>= 1) d += __shfl_xor_sync(0xffffffffu, d, oo);
        if (lane == 0) s2[j] = d * SCALE_F;
    }
    __syncthreads();
    float v2 = (tid < 128) ? s2[tid] : -FLT_MAX;
    float m2 = bredMax(v2, red);
    float e2 = (tid < 128) ? expf(s2[tid] - m2) : 0.f;
    if (tid < 128) s2[tid] = e2;
    float sum2 = bredSum(e2, red);
    __syncthreads();
    {
        float acc = 0.f;
        for (int j = half * 64; j < half * 64 + 64; j++) {
            int g = c * 512 + 448 + j; if (g > Ln - 1) g = Ln - 1;
            acc += s2[j] * __half2float(px[(size_t)g * Dn + o]);
        }
        av[half][o] = acc;
    }
    __syncthreads();
    if (tid < 128) {
        fused[128 + tid] = (av[0][tid] + av[1][tid]) / sum2;
        fused[256 + tid] = q[tid];
    }
    __syncthreads();

    {
        float acc = 0.f;
        for (int f = half * 192; f < half * 192 + 192; f++)
            acc += fused[f] * fw[f * Dn + o];
        av[half][o] = acc;
    }
    __syncthreads();
    if (tid < 128) {
        float r = av[0][tid] + av[1][tid] + fb[tid];
        int idx = n * Dn + tid;
        out[idx] = r;
        if (dup) out[NBn * Dn + idx] = r;
    }
}

// ---------------- launch ------------------------------------------------------
extern "C" void kernel_launch(void* const* d_in, const int* in_sizes, int n_in,
                              void* d_out, int out_size) {
    const float* x        = (const float*)d_in[0];
    const float* w_lw     = (const float*)d_in[1];
    const float* b_lw     = (const float*)d_in[2];
    const float* conv_w   = (const float*)d_in[3];
    const float* conv_b   = (const float*)d_in[4];
    const float* fusion_w = (const float*)d_in[5];
    const float* fusion_b = (const float*)d_in[6];
    float* out = (float*)d_out;
    int dup = (out_size >= 2 * NBn * Dn) ? 1 : 0;

    cudaFuncSetAttribute(k_conv_h, cudaFuncAttributeMaxDynamicSharedMemorySize,
                         CONV_SMEM);

    k_prep<<<(Kc * Dn * Dn + 255) / 256, 256>>>(conv_w);
    k_init_repr<<<(NBn * Dn + 255) / 256, 256>>>();
    k_logits<<<(Bn * Ln) / 8, 256>>>(x, w_lw, b_lw);
    k_scan_scalar<<<Bn, 1024>>>();
    k_partial<<<Bn * NTILES, 128>>>(x);
    k_scan_part<<<Bn, 128>>>();
    k_prefix<<<Bn * NTILES, 128>>>(x);
    k_conv_h<<<NBn * 4, 256, CONV_SMEM>>>(conv_b);
    k_attn<<<NBn, 256>>>(fusion_w, fusion_b, out, dup);
}